// round 3
// baseline (speedup 1.0000x reference)
#include <cuda_runtime.h>

#define NG 16
#define NC 8192
#define LATX 0.78125f
#define LATY 0.78125f
#define LATZ 0.375f
#define DIAM0 ((float)(0.74 * 1.4))
#define DIAM1 ((float)(0.528 * 1.4))
#define MAXCELLS 4608
#define FULLM 0xffffffffu

// ---------------------------------------------------------------------------
// Global scratch
// ---------------------------------------------------------------------------
__device__ float g_ppos[NG][NC][3];
__device__ float g_praw[NG][NC][4];
__device__ float g_qp[NG][NC];
__device__ unsigned long long g_key[NG][NC];
__device__ float g_tpos[NG][NC][3];
__device__ float g_traw[NG][NC][4];
__device__ float g_qt[NG][NC];

__device__ int g_pc[NG][NC];                 // pred cell id (masked order)
__device__ int g_cstart[NG][MAXCELLS + 1];
// cell-sorted pred SoA
__device__ float g_sx[NG][NC], g_sy[NG][NC], g_sz[NG][NC], g_sq[NG][NC];
__device__ unsigned long long g_skey[NG][NC];
__device__ int g_sorig[NG][NC], g_scell[NG][NC];
__device__ unsigned char g_r0s[NG][NC], g_keeps[NG][NC];   // by cell-order idx

__device__ unsigned long long g_kkey[NG][NC];

// sorted kept
__device__ float g_npos[NG][NC][3];
__device__ float g_nq[NG][NC];
__device__ int   g_nsrc[NG][NC];
__device__ int g_kcell[NG][NC];
__device__ int g_kstart[NG][MAXCELLS + 1];
// cell-sorted kept SoA
__device__ float g_kxx[NG][NC], g_kyy[NG][NC], g_kzz[NG][NC], g_kqq[NG][NC];
__device__ int g_klist[NG][NC];

__device__ int g_m[NG][NC], g_piv[NG][NC], g_mn[NG][NC], g_pinv[NG][NC];
__device__ int g_ti[NG][NC], g_pi[NG][NC], g_tin[NG][NC], g_pin[NG][NC];
__device__ int g_np[NG], g_nt[NG], g_nn[NG], g_k[NG], g_kn[NG];
__device__ long long g_base[NG];

// ---------------------------------------------------------------------------
// Helpers
// ---------------------------------------------------------------------------
__device__ __forceinline__ void gdims(int e, int& CX, int& CY, int& CZ) {
    if (e) { CX = 33; CY = 33; CZ = 4; } else { CX = 24; CY = 24; CZ = 2; }
}

__device__ __forceinline__ float sqnorm3(float x, float y, float z) {
    return __fadd_rn(__fadd_rn(__fmul_rn(x, x), __fmul_rn(y, y)), __fmul_rn(z, z));
}

__device__ __forceinline__ float dist2(float qi, float qj,
                                       float xi, float yi, float zi,
                                       float xj, float yj, float zj) {
    float ab = __fmul_rn(xi, xj);
    ab = fmaf(yi, yj, ab);
    ab = fmaf(zi, zj, ab);
    return __fsub_rn(__fadd_rn(qi, qj), __fmul_rn(2.0f, ab));
}

// smallest S with sqrtf(S) >= D (device-sqrt calibrated)
__device__ __forceinline__ float sqr_thresh(float D) {
    float s = __fmul_rn(D, D);
    while (sqrtf(s) < D) s = __uint_as_float(__float_as_uint(s) + 1u);
    for (;;) {
        float sm = __uint_as_float(__float_as_uint(s) - 1u);
        if (sqrtf(sm) >= D) s = sm; else break;
    }
    return s;
}

// ---------------------------------------------------------------------------
// Fused per-group pipeline: one block of 1024 threads per group
// ---------------------------------------------------------------------------
__global__ void __launch_bounds__(1024, 1)
k_group(const float* __restrict__ pred, const float* __restrict__ tgt) {
    const int g = blockIdx.x;
    const int b = g >> 1, e = g & 1;
    const int tid = threadIdx.x, lane = tid & 31, wid = tid >> 5;

    int CX, CY, CZ; gdims(e, CX, CY, CZ);
    const int NCELL = CX * CY * CZ;
    const float D = e ? DIAM1 : DIAM0;
    const float S2 = sqr_thresh(D);
    const float fx = CX / 25.0f, fy = CY / 25.0f, fz = CZ / 3.0f;

    __shared__ __align__(8) unsigned char buf[32768];   // sk (32KB) / cnt (18.5KB)
    unsigned long long* sk = (unsigned long long*)buf;
    int* cnt = (int*)buf;
    __shared__ int s_w1[32], s_w2[32];
    __shared__ int s_base1, s_base2;
    __shared__ int s_warpsum[32];
    __shared__ int s_cnt0;

    // ---------------- Stage A: mask + stable compact ----------------
    if (tid == 0) { s_base1 = 0; s_base2 = 0; }
    __syncthreads();
    for (int cb = 0; cb < NC; cb += 1024) {
        int cell = cb + tid;
        int i = cell >> 8, j = (cell >> 3) & 31, k = cell & 7;
        int inIdx = ((((b * 32 + i) * 32 + j) * 8 + k) * 2 + e) * 4;
        float p0 = pred[inIdx + 0], p1 = pred[inIdx + 1];
        float p2 = pred[inIdx + 2], p3 = pred[inIdx + 3];
        float t0 = tgt[inIdx + 0],  t1 = tgt[inIdx + 1];
        float t2 = tgt[inIdx + 2],  t3 = tgt[inIdx + 3];

        int mp = p3 > 0.5f;
        int mt = t3 > 0.5f;
        unsigned bp = __ballot_sync(FULLM, mp);
        unsigned bt = __ballot_sync(FULLM, mt);
        if (lane == 0) { s_w1[wid] = __popc(bp); s_w2[wid] = __popc(bt); }
        __syncthreads();
        int offp = s_base1, offt = s_base2;
        for (int x = 0; x < wid; x++) { offp += s_w1[x]; offt += s_w2[x]; }
        offp += __popc(bp & ((1u << lane) - 1u));
        offt += __popc(bt & ((1u << lane) - 1u));
        if (mp) {
            float px = __fmul_rn(__fadd_rn(p0, (float)i), LATX);
            float py = __fmul_rn(__fadd_rn(p1, (float)j), LATY);
            float pz = __fmul_rn(__fadd_rn(p2, (float)k), LATZ);
            g_praw[g][offp][0] = p0; g_praw[g][offp][1] = p1;
            g_praw[g][offp][2] = p2; g_praw[g][offp][3] = p3;
            g_ppos[g][offp][0] = px; g_ppos[g][offp][1] = py; g_ppos[g][offp][2] = pz;
            g_qp[g][offp] = sqnorm3(px, py, pz);
            g_key[g][offp] = ((unsigned long long)__float_as_uint(p3) << 32) | (unsigned)offp;
        }
        if (mt) {
            float tx = __fmul_rn(__fadd_rn(t0, (float)i), LATX);
            float ty = __fmul_rn(__fadd_rn(t1, (float)j), LATY);
            float tz = __fmul_rn(__fadd_rn(t2, (float)k), LATZ);
            g_traw[g][offt][0] = t0; g_traw[g][offt][1] = t1;
            g_traw[g][offt][2] = t2; g_traw[g][offt][3] = t3;
            g_tpos[g][offt][0] = tx; g_tpos[g][offt][1] = ty; g_tpos[g][offt][2] = tz;
            g_qt[g][offt] = sqnorm3(tx, ty, tz);
        }
        __syncthreads();
        if (tid == 0) {
            int sp = 0, st = 0;
            for (int x = 0; x < 32; x++) { sp += s_w1[x]; st += s_w2[x]; }
            s_base1 += sp; s_base2 += st;
        }
        __syncthreads();
    }
    const int Np = s_base1, Nt = s_base2;

    // ---------------- Stage B: pred grid (cell-sorted SoA) ----------------
    for (int c = tid; c < NCELL; c += 1024) cnt[c] = 0;
    __syncthreads();
    for (int i = tid; i < Np; i += 1024) {
        int cx = min(max((int)(g_ppos[g][i][0] * fx), 0), CX - 1);
        int cy = min(max((int)(g_ppos[g][i][1] * fy), 0), CY - 1);
        int cz = min(max((int)(g_ppos[g][i][2] * fz), 0), CZ - 1);
        int c = (cx * CY + cy) * CZ + cz;
        g_pc[g][i] = c;
        atomicAdd(&cnt[c], 1);
    }
    __syncthreads();
    // block exclusive scan of cnt[0..NCELL)
    {
        const int CH = 5;  // ceil(4608/1024)
        int lo = tid * CH, hi = min(lo + CH, NCELL);
        int acc = 0;
        for (int c = lo; c < hi; c++) acc += cnt[c];
        int v = acc;
        #pragma unroll
        for (int o = 1; o < 32; o <<= 1) { int t = __shfl_up_sync(FULLM, v, o); if (lane >= o) v += t; }
        if (lane == 31) s_warpsum[wid] = v;
        __syncthreads();
        if (wid == 0) {
            int wv = s_warpsum[lane];
            int w2 = wv;
            #pragma unroll
            for (int o = 1; o < 32; o <<= 1) { int t = __shfl_up_sync(FULLM, w2, o); if (lane >= o) w2 += t; }
            s_warpsum[lane] = w2 - wv;
        }
        __syncthreads();
        int run = (v - acc) + s_warpsum[wid];
        for (int c = lo; c < hi; c++) { int t = cnt[c]; g_cstart[g][c] = run; cnt[c] = run; run += t; }
        if (tid == 0) g_cstart[g][NCELL] = Np;
    }
    __syncthreads();
    for (int i = tid; i < Np; i += 1024) {
        int c = g_pc[g][i];
        int p = atomicAdd(&cnt[c], 1);
        g_sx[g][p] = g_ppos[g][i][0];
        g_sy[g][p] = g_ppos[g][i][1];
        g_sz[g][p] = g_ppos[g][i][2];
        g_sq[g][p] = g_qp[g][i];
        g_skey[g][p] = g_key[g][i];
        g_sorig[g][p] = i;
        g_scell[g][p] = c;
    }
    __syncthreads();

    // ---------------- Stage C: restrain==0 flags ----------------
    for (int jj = tid; jj < Np; jj += 1024) {
        float xj = g_sx[g][jj], yj = g_sy[g][jj], zj = g_sz[g][jj], qj = g_sq[g][jj];
        unsigned long long kj = g_skey[g][jj];
        int c = g_scell[g][jj];
        int cz = c % CZ, cy = (c / CZ) % CY, cx = c / (CZ * CY);
        int res = 1;
        for (int ax = max(cx - 1, 0); ax <= min(cx + 1, CX - 1) && res; ax++)
        for (int ay = max(cy - 1, 0); ay <= min(cy + 1, CY - 1) && res; ay++)
        for (int az = max(cz - 1, 0); az <= min(cz + 1, CZ - 1) && res; az++) {
            int cc = (ax * CY + ay) * CZ + az;
            int p1 = g_cstart[g][cc + 1];
            for (int p = g_cstart[g][cc]; p < p1; p++) {
                if (g_skey[g][p] < kj) {
                    float s = dist2(g_sq[g][p], qj, g_sx[g][p], g_sy[g][p], g_sz[g][p],
                                    xj, yj, zj);
                    if (s < S2) { res = 0; break; }
                }
            }
        }
        g_r0s[g][jj] = (unsigned char)res;
    }
    __syncthreads();

    // ---------------- Stage D: sel flags ----------------
    for (int jj = tid; jj < Np; jj += 1024) {
        float xj = g_sx[g][jj], yj = g_sy[g][jj], zj = g_sz[g][jj], qj = g_sq[g][jj];
        unsigned long long kj = g_skey[g][jj];
        int c = g_scell[g][jj];
        int cz = c % CZ, cy = (c / CZ) % CY, cx = c / (CZ * CY);
        int keep = 1;
        for (int ax = max(cx - 1, 0); ax <= min(cx + 1, CX - 1) && keep; ax++)
        for (int ay = max(cy - 1, 0); ay <= min(cy + 1, CY - 1) && keep; ay++)
        for (int az = max(cz - 1, 0); az <= min(cz + 1, CZ - 1) && keep; az++) {
            int cc = (ax * CY + ay) * CZ + az;
            int p1 = g_cstart[g][cc + 1];
            for (int p = g_cstart[g][cc]; p < p1; p++) {
                if (g_r0s[g][p] && g_skey[g][p] < kj) {
                    float s = dist2(g_sq[g][p], qj, g_sx[g][p], g_sy[g][p], g_sz[g][p],
                                    xj, yj, zj);
                    if (s < S2) { keep = 0; break; }
                }
            }
        }
        g_keeps[g][jj] = (unsigned char)keep;
    }
    __syncthreads();

    // ---------------- Stage E: collect kept keys (order-free) ----------------
    if (tid == 0) s_cnt0 = 0;
    __syncthreads();
    for (int jj = tid; jj < Np; jj += 1024) {
        if (g_keeps[g][jj]) {
            int p = atomicAdd(&s_cnt0, 1);
            g_kkey[g][p] = g_skey[g][jj];
        }
    }
    __syncthreads();
    const int nk = s_cnt0;
    __syncthreads();   // everyone has nk; buf about to be reused as sk

    // ---------------- Stage F: sort kept keys ascending ----------------
    if (nk <= 4096) {
        for (int i = tid; i < 4096; i += 1024) sk[i] = (i < nk) ? g_kkey[g][i] : ~0ull;
        __syncthreads();
        for (int k = 2; k <= 4096; k <<= 1)
            for (int j = k >> 1; j > 0; j >>= 1) {
                for (int i = tid; i < 4096; i += 1024) {
                    int l = i ^ j;
                    if (l > i) {
                        unsigned long long a = sk[i], bb = sk[l];
                        bool asc = ((i & k) == 0);
                        if ((a > bb) == asc) { sk[i] = bb; sk[l] = a; }
                    }
                }
                __syncthreads();
            }
        for (int r = tid; r < nk; r += 1024) {
            int src = (int)(sk[r] & 0xffffffffull);
            g_nsrc[g][r] = src;
            g_npos[g][r][0] = g_ppos[g][src][0];
            g_npos[g][r][1] = g_ppos[g][src][1];
            g_npos[g][r][2] = g_ppos[g][src][2];
            g_nq[g][r] = g_qp[g][src];
        }
    } else {
        for (int i = tid; i < nk; i += 1024) {
            unsigned long long ki = g_kkey[g][i];
            int rank = 0;
            for (int j2 = 0; j2 < nk; j2++) rank += (g_kkey[g][j2] < ki);
            int src = (int)(ki & 0xffffffffull);
            g_nsrc[g][rank] = src;
            g_npos[g][rank][0] = g_ppos[g][src][0];
            g_npos[g][rank][1] = g_ppos[g][src][1];
            g_npos[g][rank][2] = g_ppos[g][src][2];
            g_nq[g][rank] = g_qp[g][src];
        }
    }
    __syncthreads();

    // ---------------- Stage F2: kept grid (cell-sorted SoA) ----------------
    for (int c = tid; c < NCELL; c += 1024) cnt[c] = 0;
    __syncthreads();
    for (int r = tid; r < nk; r += 1024) {
        int cx = min(max((int)(g_npos[g][r][0] * fx), 0), CX - 1);
        int cy = min(max((int)(g_npos[g][r][1] * fy), 0), CY - 1);
        int cz = min(max((int)(g_npos[g][r][2] * fz), 0), CZ - 1);
        int c = (cx * CY + cy) * CZ + cz;
        g_kcell[g][r] = c;
        atomicAdd(&cnt[c], 1);
    }
    __syncthreads();
    {
        const int CH = 5;
        int lo = tid * CH, hi = min(lo + CH, NCELL);
        int acc = 0;
        for (int c = lo; c < hi; c++) acc += cnt[c];
        int v = acc;
        #pragma unroll
        for (int o = 1; o < 32; o <<= 1) { int t = __shfl_up_sync(FULLM, v, o); if (lane >= o) v += t; }
        if (lane == 31) s_warpsum[wid] = v;
        __syncthreads();
        if (wid == 0) {
            int wv = s_warpsum[lane];
            int w2 = wv;
            #pragma unroll
            for (int o = 1; o < 32; o <<= 1) { int t = __shfl_up_sync(FULLM, w2, o); if (lane >= o) w2 += t; }
            s_warpsum[lane] = w2 - wv;
        }
        __syncthreads();
        int run = (v - acc) + s_warpsum[wid];
        for (int c = lo; c < hi; c++) { int t = cnt[c]; g_kstart[g][c] = run; cnt[c] = run; run += t; }
        if (tid == 0) g_kstart[g][NCELL] = nk;
    }
    __syncthreads();
    for (int r = tid; r < nk; r += 1024) {
        int c = g_kcell[g][r];
        int p = atomicAdd(&cnt[c], 1);
        g_kxx[g][p] = g_npos[g][r][0];
        g_kyy[g][p] = g_npos[g][r][1];
        g_kzz[g][p] = g_npos[g][r][2];
        g_kqq[g][p] = g_nq[g][r];
        g_klist[g][p] = r;
    }
    __syncthreads();

    // ---------------- Stage G: match ----------------
    for (int t = tid; t < Nt; t += 1024) {
        float tx = g_tpos[g][t][0], ty = g_tpos[g][t][1], tz = g_tpos[g][t][2];
        float qt = g_qt[g][t];
        int cx = min(max((int)(tx * fx), 0), CX - 1);
        int cy = min(max((int)(ty * fy), 0), CY - 1);
        int cz = min(max((int)(tz * fz), 0), CZ - 1);

        // vs all preds
        {
            int any = 0; float bs = __int_as_float(0x7f800000); int bi = 0x7fffffff;
            for (int ax = max(cx - 1, 0); ax <= min(cx + 1, CX - 1); ax++)
            for (int ay = max(cy - 1, 0); ay <= min(cy + 1, CY - 1); ay++)
            for (int az = max(cz - 1, 0); az <= min(cz + 1, CZ - 1); az++) {
                int c = (ax * CY + ay) * CZ + az;
                int p1 = g_cstart[g][c + 1];
                for (int p = g_cstart[g][c]; p < p1; p++) {
                    float s = dist2(qt, g_sq[g][p], tx, ty, tz,
                                    g_sx[g][p], g_sy[g][p], g_sz[g][p]);
                    s = fmaxf(s, 0.0f);
                    int jj = g_sorig[g][p];
                    any |= (s < S2);
                    if (s < bs) {
                        bi = (sqrtf(s) == sqrtf(bs)) ? min(bi, jj) : jj;
                        bs = s;
                    } else if (jj < bi && s <= __fmul_rn(bs, 1.000001f)) {
                        if (sqrtf(s) == sqrtf(bs)) bi = jj;
                    }
                }
            }
            g_m[g][t] = any; g_piv[g][t] = (bi == 0x7fffffff) ? 0 : bi;
        }
        // vs NMS-kept
        {
            int any = 0; float bs = __int_as_float(0x7f800000); int bi = 0x7fffffff;
            for (int ax = max(cx - 1, 0); ax <= min(cx + 1, CX - 1); ax++)
            for (int ay = max(cy - 1, 0); ay <= min(cy + 1, CY - 1); ay++)
            for (int az = max(cz - 1, 0); az <= min(cz + 1, CZ - 1); az++) {
                int c = (ax * CY + ay) * CZ + az;
                int p1 = g_kstart[g][c + 1];
                for (int p = g_kstart[g][c]; p < p1; p++) {
                    float s = dist2(qt, g_kqq[g][p], tx, ty, tz,
                                    g_kxx[g][p], g_kyy[g][p], g_kzz[g][p]);
                    s = fmaxf(s, 0.0f);
                    int jj = g_klist[g][p];
                    any |= (s < S2);
                    if (s < bs) {
                        bi = (sqrtf(s) == sqrtf(bs)) ? min(bi, jj) : jj;
                        bs = s;
                    } else if (jj < bi && s <= __fmul_rn(bs, 1.000001f)) {
                        if (sqrtf(s) == sqrtf(bs)) bi = jj;
                    }
                }
            }
            g_mn[g][t] = any; g_pinv[g][t] = (bi == 0x7fffffff) ? 0 : bi;
        }
    }
    __syncthreads();

    // ---------------- Stage H: compact matches ----------------
    for (int pass = 0; pass < 2; pass++) {
        if (tid == 0) s_base1 = 0;
        __syncthreads();
        for (int cb = 0; cb < Nt; cb += 1024) {
            int t = cb + tid;
            int f = 0;
            if (t < Nt) f = pass ? g_mn[g][t] : g_m[g][t];
            unsigned bl = __ballot_sync(FULLM, f != 0);
            if (lane == 0) s_w1[wid] = __popc(bl);
            __syncthreads();
            int off = s_base1;
            for (int x = 0; x < wid; x++) off += s_w1[x];
            off += __popc(bl & ((1u << lane) - 1u));
            if (f) {
                if (pass) { g_tin[g][off] = t; g_pin[g][off] = g_pinv[g][t]; }
                else      { g_ti[g][off]  = t; g_pi[g][off]  = g_piv[g][t]; }
            }
            __syncthreads();
            if (tid == 0) { int s = 0; for (int x = 0; x < 32; x++) s += s_w1[x]; s_base1 += s; }
            __syncthreads();
        }
        if (tid == 0) { if (pass) g_kn[g] = s_base1; else g_k[g] = s_base1; }
        __syncthreads();
    }

    if (tid == 0) { g_np[g] = Np; g_nt[g] = Nt; g_nn[g] = nk; }
}

// ---------------------------------------------------------------------------
// Offsets + write
// ---------------------------------------------------------------------------
__global__ void k_offsets() {
    long long base = 0;
    for (int g = 0; g < NG; g++) {
        g_base[g] = base;
        long long Np = g_np[g], Nn = g_nn[g], Nt = g_nt[g], K = g_k[g], Kn = g_kn[g];
        base += Np * 4 + Nn * 4 + Nt * 4 + 2 * K + 2 * Kn + Np * 3 + Nn * 3 + Nt * 3;
    }
}

__global__ void k_write(float* __restrict__ out) {
    int g = blockIdx.y;
    long long base = g_base[g];
    int Np = g_np[g], Nn = g_nn[g], Nt = g_nt[g], K = g_k[g], Kn = g_kn[g];
    int T = Np * 4 + Nn * 4 + Nt * 4 + 2 * K + 2 * Kn + Np * 3 + Nn * 3 + Nt * 3;
    int stride = gridDim.x * blockDim.x;
    for (int idx = blockIdx.x * blockDim.x + threadIdx.x; idx < T; idx += stride) {
        int o = idx;
        float v;
        if (o < Np * 4) { v = g_praw[g][o >> 2][o & 3]; }
        else {
            o -= Np * 4;
            if (o < Nn * 4) { v = g_praw[g][g_nsrc[g][o >> 2]][o & 3]; }
            else {
                o -= Nn * 4;
                if (o < Nt * 4) { v = g_traw[g][o >> 2][o & 3]; }
                else {
                    o -= Nt * 4;
                    if (o < K) { v = (float)g_ti[g][o]; }
                    else {
                        o -= K;
                        if (o < K) { v = (float)g_pi[g][o]; }
                        else {
                            o -= K;
                            if (o < Kn) { v = (float)g_tin[g][o]; }
                            else {
                                o -= Kn;
                                if (o < Kn) { v = (float)g_pin[g][o]; }
                                else {
                                    o -= Kn;
                                    if (o < Np * 3) { v = g_ppos[g][o / 3][o % 3]; }
                                    else {
                                        o -= Np * 3;
                                        if (o < Nn * 3) { v = g_npos[g][o / 3][o % 3]; }
                                        else { o -= Nn * 3; v = g_tpos[g][o / 3][o % 3]; }
                                    }
                                }
                            }
                        }
                    }
                }
            }
        }
        out[base + idx] = v;
    }
}

// ---------------------------------------------------------------------------
// launch: 3 graph nodes
// ---------------------------------------------------------------------------
extern "C" void kernel_launch(void* const* d_in, const int* in_sizes, int n_in,
                              void* d_out, int out_size) {
    const float* pred = (const float*)d_in[0];
    const float* tgt  = (const float*)d_in[1];
    float* out = (float*)d_out;
    (void)in_sizes; (void)n_in; (void)out_size;

    k_group<<<NG, 1024>>>(pred, tgt);
    k_offsets<<<1, 1>>>();
    k_write<<<dim3(32, NG), 256>>>(out);
}

// round 4
// speedup vs baseline: 2.5346x; 2.5346x over previous
#include <cuda_runtime.h>

#define NG 16
#define NC 8192
#define LATX 0.78125f
#define LATY 0.78125f
#define LATZ 0.375f
#define DIAM0 ((float)(0.74 * 1.4))
#define DIAM1 ((float)(0.528 * 1.4))
#define MAXCELLS 4608
#define FULLM 0xffffffffu

// ---------------------------------------------------------------------------
// Global scratch
// ---------------------------------------------------------------------------
__device__ float g_ppos[NG][NC][3];
__device__ float g_praw[NG][NC][4];
__device__ float g_qp[NG][NC];
__device__ float g_tpos[NG][NC][3];
__device__ float g_traw[NG][NC][4];
__device__ float g_qt[NG][NC];

__device__ int g_cstart[NG][MAXCELLS + 1];
// cell-sorted pred SoA
__device__ float g_sx[NG][NC], g_sy[NG][NC], g_sz[NG][NC], g_sq[NG][NC];
__device__ unsigned long long g_skey[NG][NC];
__device__ int g_sorig[NG][NC], g_scell[NG][NC];
__device__ unsigned char g_r0s[NG][NC], g_keeps[NG][NC];

__device__ unsigned long long g_kkey[NG][NC];

// key-sorted kept
__device__ float g_npos[NG][NC][3];
__device__ float g_nq[NG][NC];
__device__ int   g_nsrc[NG][NC];
__device__ int g_kstart[NG][MAXCELLS + 1];
// cell-sorted kept SoA
__device__ float g_kxx[NG][NC], g_kyy[NG][NC], g_kzz[NG][NC], g_kqq[NG][NC];
__device__ int g_klist[NG][NC];

__device__ int g_m[NG][NC], g_piv[NG][NC], g_mn[NG][NC], g_pinv[NG][NC];
__device__ int g_ti[NG][NC], g_pi[NG][NC], g_tin[NG][NC], g_pin[NG][NC];
__device__ int g_np[NG], g_nt[NG], g_nn[NG], g_k[NG], g_kn[NG];
__device__ long long g_base[NG];

// ---------------------------------------------------------------------------
// Helpers
// ---------------------------------------------------------------------------
__device__ __forceinline__ void gdims(int e, int& CX, int& CY, int& CZ) {
    if (e) { CX = 33; CY = 33; CZ = 4; } else { CX = 24; CY = 24; CZ = 2; }
}

__device__ __forceinline__ float sqnorm3(float x, float y, float z) {
    return __fadd_rn(__fadd_rn(__fmul_rn(x, x), __fmul_rn(y, y)), __fmul_rn(z, z));
}

__device__ __forceinline__ float dist2(float qi, float qj,
                                       float xi, float yi, float zi,
                                       float xj, float yj, float zj) {
    float ab = __fmul_rn(xi, xj);
    ab = fmaf(yi, yj, ab);
    ab = fmaf(zi, zj, ab);
    return __fsub_rn(__fadd_rn(qi, qj), __fmul_rn(2.0f, ab));
}

__device__ __forceinline__ float sqr_thresh(float D) {
    float s = __fmul_rn(D, D);
    while (sqrtf(s) < D) s = __uint_as_float(__float_as_uint(s) + 1u);
    for (;;) {
        float sm = __uint_as_float(__float_as_uint(s) - 1u);
        if (sqrtf(sm) >= D) s = sm; else break;
    }
    return s;
}

// ---------------------------------------------------------------------------
// K1 (NG blocks x 1024): compact + pred grid build (cell-sorted SoA)
// ---------------------------------------------------------------------------
__global__ void __launch_bounds__(1024, 1)
k_pre(const float* __restrict__ pred, const float* __restrict__ tgt) {
    const int g = blockIdx.x;
    const int b = g >> 1, e = g & 1;
    const int tid = threadIdx.x, lane = tid & 31, wid = tid >> 5;

    int CX, CY, CZ; gdims(e, CX, CY, CZ);
    const int NCELL = CX * CY * CZ;
    const float fx = CX / 25.0f, fy = CY / 25.0f, fz = CZ / 3.0f;

    __shared__ int cnt[MAXCELLS];
    __shared__ int s_w1[32], s_w2[32];
    __shared__ int s_base1, s_base2;
    __shared__ int s_warpsum[32];

    const float4* p4 = (const float4*)pred;
    const float4* t4 = (const float4*)tgt;

    if (tid == 0) { s_base1 = 0; s_base2 = 0; }
    __syncthreads();
    for (int cb = 0; cb < NC; cb += 1024) {
        int cell = cb + tid;
        int i = cell >> 8, j = (cell >> 3) & 31, k = cell & 7;
        float4 pv = p4[(b * NC + cell) * 2 + e];
        float4 tv = t4[(b * NC + cell) * 2 + e];

        int mp = pv.w > 0.5f;
        int mt = tv.w > 0.5f;
        unsigned bp = __ballot_sync(FULLM, mp);
        unsigned bt = __ballot_sync(FULLM, mt);
        if (lane == 0) { s_w1[wid] = __popc(bp); s_w2[wid] = __popc(bt); }
        __syncthreads();
        int offp = s_base1, offt = s_base2;
        for (int x = 0; x < wid; x++) { offp += s_w1[x]; offt += s_w2[x]; }
        offp += __popc(bp & ((1u << lane) - 1u));
        offt += __popc(bt & ((1u << lane) - 1u));
        if (mp) {
            float px = __fmul_rn(__fadd_rn(pv.x, (float)i), LATX);
            float py = __fmul_rn(__fadd_rn(pv.y, (float)j), LATY);
            float pz = __fmul_rn(__fadd_rn(pv.z, (float)k), LATZ);
            ((float4*)g_praw[g])[offp] = pv;
            g_ppos[g][offp][0] = px; g_ppos[g][offp][1] = py; g_ppos[g][offp][2] = pz;
            g_qp[g][offp] = sqnorm3(px, py, pz);
        }
        if (mt) {
            float tx = __fmul_rn(__fadd_rn(tv.x, (float)i), LATX);
            float ty = __fmul_rn(__fadd_rn(tv.y, (float)j), LATY);
            float tz = __fmul_rn(__fadd_rn(tv.z, (float)k), LATZ);
            ((float4*)g_traw[g])[offt] = tv;
            g_tpos[g][offt][0] = tx; g_tpos[g][offt][1] = ty; g_tpos[g][offt][2] = tz;
            g_qt[g][offt] = sqnorm3(tx, ty, tz);
        }
        __syncthreads();
        if (tid == 0) {
            int sp = 0, st = 0;
            for (int x = 0; x < 32; x++) { sp += s_w1[x]; st += s_w2[x]; }
            s_base1 += sp; s_base2 += st;
        }
        __syncthreads();
    }
    const int Np = s_base1, Nt = s_base2;

    // grid build
    for (int c = tid; c < NCELL; c += 1024) cnt[c] = 0;
    __syncthreads();
    for (int i = tid; i < Np; i += 1024) {
        int cx = min(max((int)(g_ppos[g][i][0] * fx), 0), CX - 1);
        int cy = min(max((int)(g_ppos[g][i][1] * fy), 0), CY - 1);
        int cz = min(max((int)(g_ppos[g][i][2] * fz), 0), CZ - 1);
        atomicAdd(&cnt[(cx * CY + cy) * CZ + cz], 1);
    }
    __syncthreads();
    {
        const int CH = 5;
        int lo = tid * CH, hi = min(lo + CH, NCELL);
        int acc = 0;
        for (int c = lo; c < hi; c++) acc += cnt[c];
        int v = acc;
        #pragma unroll
        for (int o = 1; o < 32; o <<= 1) { int t = __shfl_up_sync(FULLM, v, o); if (lane >= o) v += t; }
        if (lane == 31) s_warpsum[wid] = v;
        __syncthreads();
        if (wid == 0) {
            int wv = s_warpsum[lane];
            int w2 = wv;
            #pragma unroll
            for (int o = 1; o < 32; o <<= 1) { int t = __shfl_up_sync(FULLM, w2, o); if (lane >= o) w2 += t; }
            s_warpsum[lane] = w2 - wv;
        }
        __syncthreads();
        int run = (v - acc) + s_warpsum[wid];
        for (int c = lo; c < hi; c++) { int t = cnt[c]; g_cstart[g][c] = run; cnt[c] = run; run += t; }
        if (tid == 0) g_cstart[g][NCELL] = Np;
    }
    __syncthreads();
    for (int i = tid; i < Np; i += 1024) {
        int cx = min(max((int)(g_ppos[g][i][0] * fx), 0), CX - 1);
        int cy = min(max((int)(g_ppos[g][i][1] * fy), 0), CY - 1);
        int cz = min(max((int)(g_ppos[g][i][2] * fz), 0), CZ - 1);
        int c = (cx * CY + cy) * CZ + cz;
        int p = atomicAdd(&cnt[c], 1);
        g_sx[g][p] = g_ppos[g][i][0];
        g_sy[g][p] = g_ppos[g][i][1];
        g_sz[g][p] = g_ppos[g][i][2];
        g_sq[g][p] = g_qp[g][i];
        g_skey[g][p] = ((unsigned long long)__float_as_uint(g_praw[g][i][3]) << 32) | (unsigned)i;
        g_sorig[g][p] = i;
        g_scell[g][p] = c;
    }
    if (tid == 0) { g_np[g] = Np; g_nt[g] = Nt; }
}

// ---------------------------------------------------------------------------
// K2/K3 wide: restrain==0 / sel flags (9 contiguous z-collapsed ranges)
// ---------------------------------------------------------------------------
template<int CHECK_R0>
__device__ __forceinline__ void flagScan(int g, int jj, int CX, int CY, int CZ, float S2,
                                         unsigned char* outFlag) {
    float xj = g_sx[g][jj], yj = g_sy[g][jj], zj = g_sz[g][jj], qj = g_sq[g][jj];
    unsigned long long kj = g_skey[g][jj];
    int c = g_scell[g][jj];
    int cz = c % CZ, cy = (c / CZ) % CY, cx = c / (CZ * CY);
    int z0 = max(cz - 1, 0), z1 = min(cz + 1, CZ - 1);
    int ok = 1;
    for (int ax = max(cx - 1, 0); ax <= min(cx + 1, CX - 1) && ok; ax++)
    for (int ay = max(cy - 1, 0); ay <= min(cy + 1, CY - 1) && ok; ay++) {
        int rowc = (ax * CY + ay) * CZ;
        int p1 = g_cstart[g][rowc + z1 + 1];
        for (int p = g_cstart[g][rowc + z0]; p < p1; p++) {
            if (CHECK_R0 && !g_r0s[g][p]) continue;
            if (g_skey[g][p] < kj) {
                float s = dist2(g_sq[g][p], qj, g_sx[g][p], g_sy[g][p], g_sz[g][p],
                                xj, yj, zj);
                if (s < S2) { ok = 0; break; }
            }
        }
    }
    outFlag[jj] = (unsigned char)ok;
}

__global__ void k_res0() {
    int g = blockIdx.y;
    int jj = blockIdx.x * blockDim.x + threadIdx.x;
    if (jj >= g_np[g]) return;
    int e = g & 1;
    int CX, CY, CZ; gdims(e, CX, CY, CZ);
    float S2 = sqr_thresh(e ? DIAM1 : DIAM0);
    flagScan<0>(g, jj, CX, CY, CZ, S2, g_r0s[g]);
}

__global__ void k_sel() {
    int g = blockIdx.y;
    int jj = blockIdx.x * blockDim.x + threadIdx.x;
    if (jj >= g_np[g]) return;
    int e = g & 1;
    int CX, CY, CZ; gdims(e, CX, CY, CZ);
    float S2 = sqr_thresh(e ? DIAM1 : DIAM0);
    flagScan<1>(g, jj, CX, CY, CZ, S2, g_keeps[g]);
}

// ---------------------------------------------------------------------------
// K4 (NG blocks x 1024): kept-compact + key sort + kept grid (SoA)
// ---------------------------------------------------------------------------
__global__ void __launch_bounds__(1024, 1)
k_mid() {
    const int g = blockIdx.x;
    const int e = g & 1;
    const int tid = threadIdx.x, lane = tid & 31, wid = tid >> 5;
    int CX, CY, CZ; gdims(e, CX, CY, CZ);
    const int NCELL = CX * CY * CZ;
    const float fx = CX / 25.0f, fy = CY / 25.0f, fz = CZ / 3.0f;
    const int Np = g_np[g];

    __shared__ __align__(8) unsigned char buf[32768];
    unsigned long long* sk = (unsigned long long*)buf;
    int* cnt = (int*)buf;
    __shared__ int s_cnt0;
    __shared__ int s_warpsum[32];

    if (tid == 0) s_cnt0 = 0;
    __syncthreads();
    for (int jj = tid; jj < Np; jj += 1024)
        if (g_keeps[g][jj]) g_kkey[g][atomicAdd(&s_cnt0, 1)] = g_skey[g][jj];
    __syncthreads();
    const int nk = s_cnt0;
    __syncthreads();

    // sort keys ascending (bitonic over next pow2)
    if (nk <= 4096) {
        int M = 2; while (M < nk) M <<= 1;
        for (int i = tid; i < M; i += 1024) sk[i] = (i < nk) ? g_kkey[g][i] : ~0ull;
        __syncthreads();
        for (int k = 2; k <= M; k <<= 1)
            for (int j = k >> 1; j > 0; j >>= 1) {
                for (int i = tid; i < M; i += 1024) {
                    int l = i ^ j;
                    if (l > i) {
                        unsigned long long a = sk[i], bb = sk[l];
                        bool asc = ((i & k) == 0);
                        if ((a > bb) == asc) { sk[i] = bb; sk[l] = a; }
                    }
                }
                __syncthreads();
            }
        for (int r = tid; r < nk; r += 1024) {
            int src = (int)(sk[r] & 0xffffffffull);
            g_nsrc[g][r] = src;
            g_npos[g][r][0] = g_ppos[g][src][0];
            g_npos[g][r][1] = g_ppos[g][src][1];
            g_npos[g][r][2] = g_ppos[g][src][2];
            g_nq[g][r] = g_qp[g][src];
        }
    } else {
        for (int i = tid; i < nk; i += 1024) {
            unsigned long long ki = g_kkey[g][i];
            int rank = 0;
            for (int j2 = 0; j2 < nk; j2++) rank += (g_kkey[g][j2] < ki);
            int src = (int)(ki & 0xffffffffull);
            g_nsrc[g][rank] = src;
            g_npos[g][rank][0] = g_ppos[g][src][0];
            g_npos[g][rank][1] = g_ppos[g][src][1];
            g_npos[g][rank][2] = g_ppos[g][src][2];
            g_nq[g][rank] = g_qp[g][src];
        }
    }
    __syncthreads();

    // kept grid (buf reused as cnt)
    for (int c = tid; c < NCELL; c += 1024) cnt[c] = 0;
    __syncthreads();
    for (int r = tid; r < nk; r += 1024) {
        int cx = min(max((int)(g_npos[g][r][0] * fx), 0), CX - 1);
        int cy = min(max((int)(g_npos[g][r][1] * fy), 0), CY - 1);
        int cz = min(max((int)(g_npos[g][r][2] * fz), 0), CZ - 1);
        atomicAdd(&cnt[(cx * CY + cy) * CZ + cz], 1);
    }
    __syncthreads();
    {
        const int CH = 5;
        int lo = tid * CH, hi = min(lo + CH, NCELL);
        int acc = 0;
        for (int c = lo; c < hi; c++) acc += cnt[c];
        int v = acc;
        #pragma unroll
        for (int o = 1; o < 32; o <<= 1) { int t = __shfl_up_sync(FULLM, v, o); if (lane >= o) v += t; }
        if (lane == 31) s_warpsum[wid] = v;
        __syncthreads();
        if (wid == 0) {
            int wv = s_warpsum[lane];
            int w2 = wv;
            #pragma unroll
            for (int o = 1; o < 32; o <<= 1) { int t = __shfl_up_sync(FULLM, w2, o); if (lane >= o) w2 += t; }
            s_warpsum[lane] = w2 - wv;
        }
        __syncthreads();
        int run = (v - acc) + s_warpsum[wid];
        for (int c = lo; c < hi; c++) { int t = cnt[c]; g_kstart[g][c] = run; cnt[c] = run; run += t; }
        if (tid == 0) g_kstart[g][NCELL] = nk;
    }
    __syncthreads();
    for (int r = tid; r < nk; r += 1024) {
        int cx = min(max((int)(g_npos[g][r][0] * fx), 0), CX - 1);
        int cy = min(max((int)(g_npos[g][r][1] * fy), 0), CY - 1);
        int cz = min(max((int)(g_npos[g][r][2] * fz), 0), CZ - 1);
        int c = (cx * CY + cy) * CZ + cz;
        int p = atomicAdd(&cnt[c], 1);
        g_kxx[g][p] = g_npos[g][r][0];
        g_kyy[g][p] = g_npos[g][r][1];
        g_kzz[g][p] = g_npos[g][r][2];
        g_kqq[g][p] = g_nq[g][r];
        g_klist[g][p] = r;
    }
    if (tid == 0) g_nn[g] = nk;
}

// ---------------------------------------------------------------------------
// K5 wide: match (targets vs preds / vs kept), z-collapsed ranges
// ---------------------------------------------------------------------------
__global__ void k_match() {
    int g = blockIdx.y;
    int t = blockIdx.x * blockDim.x + threadIdx.x;
    if (t >= g_nt[g]) return;
    int e = g & 1;
    int CX, CY, CZ; gdims(e, CX, CY, CZ);
    float S2 = sqr_thresh(e ? DIAM1 : DIAM0);
    float fx = CX / 25.0f, fy = CY / 25.0f, fz = CZ / 3.0f;
    float tx = g_tpos[g][t][0], ty = g_tpos[g][t][1], tz = g_tpos[g][t][2];
    float qt = g_qt[g][t];
    int cx = min(max((int)(tx * fx), 0), CX - 1);
    int cy = min(max((int)(ty * fy), 0), CY - 1);
    int cz = min(max((int)(tz * fz), 0), CZ - 1);
    int z0 = max(cz - 1, 0), z1 = min(cz + 1, CZ - 1);
    int x0 = max(cx - 1, 0), x1 = min(cx + 1, CX - 1);
    int y0 = max(cy - 1, 0), y1 = min(cy + 1, CY - 1);

    {
        int any = 0; float bs = __int_as_float(0x7f800000); int bi = 0x7fffffff;
        for (int ax = x0; ax <= x1; ax++)
        for (int ay = y0; ay <= y1; ay++) {
            int rowc = (ax * CY + ay) * CZ;
            int p1 = g_cstart[g][rowc + z1 + 1];
            for (int p = g_cstart[g][rowc + z0]; p < p1; p++) {
                float s = dist2(qt, g_sq[g][p], tx, ty, tz,
                                g_sx[g][p], g_sy[g][p], g_sz[g][p]);
                s = fmaxf(s, 0.0f);
                int jj = g_sorig[g][p];
                any |= (s < S2);
                if (s < bs) {
                    bi = (sqrtf(s) == sqrtf(bs)) ? min(bi, jj) : jj;
                    bs = s;
                } else if (jj < bi && s <= __fmul_rn(bs, 1.000001f)) {
                    if (sqrtf(s) == sqrtf(bs)) bi = jj;
                }
            }
        }
        g_m[g][t] = any; g_piv[g][t] = (bi == 0x7fffffff) ? 0 : bi;
    }
    {
        int any = 0; float bs = __int_as_float(0x7f800000); int bi = 0x7fffffff;
        for (int ax = x0; ax <= x1; ax++)
        for (int ay = y0; ay <= y1; ay++) {
            int rowc = (ax * CY + ay) * CZ;
            int p1 = g_kstart[g][rowc + z1 + 1];
            for (int p = g_kstart[g][rowc + z0]; p < p1; p++) {
                float s = dist2(qt, g_kqq[g][p], tx, ty, tz,
                                g_kxx[g][p], g_kyy[g][p], g_kzz[g][p]);
                s = fmaxf(s, 0.0f);
                int jj = g_klist[g][p];
                any |= (s < S2);
                if (s < bs) {
                    bi = (sqrtf(s) == sqrtf(bs)) ? min(bi, jj) : jj;
                    bs = s;
                } else if (jj < bi && s <= __fmul_rn(bs, 1.000001f)) {
                    if (sqrtf(s) == sqrtf(bs)) bi = jj;
                }
            }
        }
        g_mn[g][t] = any; g_pinv[g][t] = (bi == 0x7fffffff) ? 0 : bi;
    }
}

// ---------------------------------------------------------------------------
// K6 (NG blocks x 256): compact matches
// ---------------------------------------------------------------------------
__global__ void k_post() {
    int g = blockIdx.x;
    int tid = threadIdx.x;
    int lane = tid & 31, w = tid >> 5;
    int Nt = g_nt[g];
    __shared__ int wt[8];
    __shared__ int base;

    for (int pass = 0; pass < 2; pass++) {
        if (tid == 0) base = 0;
        __syncthreads();
        for (int cb = 0; cb < Nt; cb += 256) {
            int t = cb + tid;
            int f = 0;
            if (t < Nt) f = pass ? g_mn[g][t] : g_m[g][t];
            unsigned bl = __ballot_sync(FULLM, f != 0);
            if (lane == 0) wt[w] = __popc(bl);
            __syncthreads();
            int off = base;
            for (int x = 0; x < w; x++) off += wt[x];
            off += __popc(bl & ((1u << lane) - 1u));
            if (f) {
                if (pass) { g_tin[g][off] = t; g_pin[g][off] = g_pinv[g][t]; }
                else      { g_ti[g][off]  = t; g_pi[g][off]  = g_piv[g][t]; }
            }
            __syncthreads();
            if (tid == 0) { int s = 0; for (int x = 0; x < 8; x++) s += wt[x]; base += s; }
            __syncthreads();
        }
        if (tid == 0) { if (pass) g_kn[g] = base; else g_k[g] = base; }
        __syncthreads();
    }
}

// ---------------------------------------------------------------------------
// K7 offsets, K8 write
// ---------------------------------------------------------------------------
__global__ void k_offsets() {
    long long base = 0;
    for (int g = 0; g < NG; g++) {
        g_base[g] = base;
        long long Np = g_np[g], Nn = g_nn[g], Nt = g_nt[g], K = g_k[g], Kn = g_kn[g];
        base += Np * 4 + Nn * 4 + Nt * 4 + 2 * K + 2 * Kn + Np * 3 + Nn * 3 + Nt * 3;
    }
}

__global__ void k_write(float* __restrict__ out) {
    int g = blockIdx.y;
    long long base = g_base[g];
    int Np = g_np[g], Nn = g_nn[g], Nt = g_nt[g], K = g_k[g], Kn = g_kn[g];
    int T = Np * 4 + Nn * 4 + Nt * 4 + 2 * K + 2 * Kn + Np * 3 + Nn * 3 + Nt * 3;
    int stride = gridDim.x * blockDim.x;
    for (int idx = blockIdx.x * blockDim.x + threadIdx.x; idx < T; idx += stride) {
        int o = idx;
        float v;
        if (o < Np * 4) { v = g_praw[g][o >> 2][o & 3]; }
        else {
            o -= Np * 4;
            if (o < Nn * 4) { v = g_praw[g][g_nsrc[g][o >> 2]][o & 3]; }
            else {
                o -= Nn * 4;
                if (o < Nt * 4) { v = g_traw[g][o >> 2][o & 3]; }
                else {
                    o -= Nt * 4;
                    if (o < K) { v = (float)g_ti[g][o]; }
                    else {
                        o -= K;
                        if (o < K) { v = (float)g_pi[g][o]; }
                        else {
                            o -= K;
                            if (o < Kn) { v = (float)g_tin[g][o]; }
                            else {
                                o -= Kn;
                                if (o < Kn) { v = (float)g_pin[g][o]; }
                                else {
                                    o -= Kn;
                                    if (o < Np * 3) { v = g_ppos[g][o / 3][o % 3]; }
                                    else {
                                        o -= Np * 3;
                                        if (o < Nn * 3) { v = g_npos[g][o / 3][o % 3]; }
                                        else { o -= Nn * 3; v = g_tpos[g][o / 3][o % 3]; }
                                    }
                                }
                            }
                        }
                    }
                }
            }
        }
        out[base + idx] = v;
    }
}

// ---------------------------------------------------------------------------
// launch: 8 graph nodes
// ---------------------------------------------------------------------------
extern "C" void kernel_launch(void* const* d_in, const int* in_sizes, int n_in,
                              void* d_out, int out_size) {
    const float* pred = (const float*)d_in[0];
    const float* tgt  = (const float*)d_in[1];
    float* out = (float*)d_out;
    (void)in_sizes; (void)n_in; (void)out_size;

    dim3 wide(32, NG);
    k_pre<<<NG, 1024>>>(pred, tgt);
    k_res0<<<wide, 256>>>();
    k_sel<<<wide, 256>>>();
    k_mid<<<NG, 1024>>>();
    k_match<<<wide, 256>>>();
    k_post<<<NG, 256>>>();
    k_offsets<<<1, 1>>>();
    k_write<<<wide, 256>>>(out);
}

// round 6
// speedup vs baseline: 2.7487x; 1.0845x over previous
#include <cuda_runtime.h>

#define NG 16
#define NC 8192
#define LATX 0.78125f
#define LATY 0.78125f
#define LATZ 0.375f
#define DIAM0 ((float)(0.74 * 1.4))
#define DIAM1 ((float)(0.528 * 1.4))
#define MAXCELLS 4608
#define NCHUNK 32          // 8192 / 256
#define FULLM 0xffffffffu

// ---------------------------------------------------------------------------
// Global scratch (zero-initialized at module load; g_ccnt kept zero by
// zero-after-use in k_scan so every graph replay sees zeros)
// ---------------------------------------------------------------------------
__device__ float g_ppos[NG][NC][3];
__device__ float g_praw[NG][NC][4];
__device__ float g_qp[NG][NC];
__device__ float g_tpos[NG][NC][3];
__device__ float g_traw[NG][NC][4];
__device__ float g_qt[NG][NC];

__device__ int g_chunkP[NG][NCHUNK], g_chunkT[NG][NCHUNK];
__device__ int g_chunkBaseP[NG][NCHUNK], g_chunkBaseT[NG][NCHUNK];
__device__ int g_ccnt[NG][MAXCELLS];          // cell histogram (zero invariant)
__device__ int g_cstart[NG][MAXCELLS + 1];
__device__ int g_cellfill[NG][MAXCELLS];

// cell-sorted pred SoA
__device__ float g_sx[NG][NC], g_sy[NG][NC], g_sz[NG][NC], g_sq[NG][NC];
__device__ unsigned long long g_skey[NG][NC];
__device__ int g_sorig[NG][NC], g_scell[NG][NC];
__device__ unsigned char g_r0s[NG][NC];

__device__ unsigned long long g_kkey[NG][NC];
__device__ int g_nkc[NG];                     // kept counter (reset in k_scan)

// key-sorted kept
__device__ float g_npos[NG][NC][3];
__device__ float g_nq[NG][NC];
__device__ int   g_nsrc[NG][NC];
__device__ int g_kstart[NG][MAXCELLS + 1];
__device__ float g_kxx[NG][NC], g_kyy[NG][NC], g_kzz[NG][NC], g_kqq[NG][NC];
__device__ int g_klist[NG][NC];

__device__ int g_m[NG][NC], g_piv[NG][NC], g_mn[NG][NC], g_pinv[NG][NC];
__device__ int g_ti[NG][NC], g_pi[NG][NC], g_tin[NG][NC], g_pin[NG][NC];
__device__ int g_np[NG], g_nt[NG], g_nn[NG], g_k[NG], g_kn[NG];

// ---------------------------------------------------------------------------
// Helpers
// ---------------------------------------------------------------------------
__device__ __forceinline__ void gdims(int e, int& CX, int& CY, int& CZ) {
    if (e) { CX = 33; CY = 33; CZ = 4; } else { CX = 24; CY = 24; CZ = 2; }
}

__device__ __forceinline__ float sqnorm3(float x, float y, float z) {
    return __fadd_rn(__fadd_rn(__fmul_rn(x, x), __fmul_rn(y, y)), __fmul_rn(z, z));
}

__device__ __forceinline__ float dist2(float qi, float qj,
                                       float xi, float yi, float zi,
                                       float xj, float yj, float zj) {
    float ab = __fmul_rn(xi, xj);
    ab = fmaf(yi, yj, ab);
    ab = fmaf(zi, zj, ab);
    return __fsub_rn(__fadd_rn(qi, qj), __fmul_rn(2.0f, ab));
}

__device__ __forceinline__ float sqr_thresh(float D) {
    float s = __fmul_rn(D, D);
    while (sqrtf(s) < D) s = __uint_as_float(__float_as_uint(s) + 1u);
    for (;;) {
        float sm = __uint_as_float(__float_as_uint(s) - 1u);
        if (sqrtf(sm) >= D) s = sm; else break;
    }
    return s;
}

__device__ __forceinline__ void cellOf(float x, float y, float z,
                                       float fx, float fy, float fz,
                                       int CX, int CY, int CZ, int& c) {
    int cx = min(max((int)(x * fx), 0), CX - 1);
    int cy = min(max((int)(y * fy), 0), CY - 1);
    int cz = min(max((int)(z * fz), 0), CZ - 1);
    c = (cx * CY + cy) * CZ + cz;
}

// ---------------------------------------------------------------------------
// K1 wide: chunk counts + cell histogram
// ---------------------------------------------------------------------------
__global__ void k_count(const float* __restrict__ pred,
                        const float* __restrict__ tgt) {
    int g = blockIdx.y, ch = blockIdx.x, tid = threadIdx.x;
    int b = g >> 1, e = g & 1;
    int CX, CY, CZ; gdims(e, CX, CY, CZ);
    float fx = CX / 25.0f, fy = CY / 25.0f, fz = CZ / 3.0f;

    int cell = ch * 256 + tid;
    int i = cell >> 8, j = (cell >> 3) & 31, k = cell & 7;
    float4 pv = ((const float4*)pred)[(b * NC + cell) * 2 + e];
    float4 tv = ((const float4*)tgt)[(b * NC + cell) * 2 + e];
    int mp = pv.w > 0.5f;
    int mt = tv.w > 0.5f;

    if (mp) {
        float px = __fmul_rn(__fadd_rn(pv.x, (float)i), LATX);
        float py = __fmul_rn(__fadd_rn(pv.y, (float)j), LATY);
        float pz = __fmul_rn(__fadd_rn(pv.z, (float)k), LATZ);
        int c; cellOf(px, py, pz, fx, fy, fz, CX, CY, CZ, c);
        atomicAdd(&g_ccnt[g][c], 1);
    }
    int cp = __syncthreads_count(mp);
    int ct = __syncthreads_count(mt);
    if (tid == 0) { g_chunkP[g][ch] = cp; g_chunkT[g][ch] = ct; }
}

// ---------------------------------------------------------------------------
// K2 (16 blocks x 1024): scans + resets
// ---------------------------------------------------------------------------
__global__ void __launch_bounds__(1024, 1) k_scan() {
    int g = blockIdx.x, tid = threadIdx.x, lane = tid & 31, wid = tid >> 5;
    int e = g & 1;
    int CX, CY, CZ; gdims(e, CX, CY, CZ);
    int NCELL = CX * CY * CZ;
    __shared__ int s_warpsum[32];

    if (tid == 0) {
        int rp = 0, rt = 0;
        for (int c = 0; c < NCHUNK; c++) {
            g_chunkBaseP[g][c] = rp; rp += g_chunkP[g][c];
            g_chunkBaseT[g][c] = rt; rt += g_chunkT[g][c];
        }
        g_np[g] = rp; g_nt[g] = rt;
        g_nkc[g] = 0;
    }

    // scan cell histogram
    const int CH = 5;
    int lo = tid * CH, hi = min(lo + CH, NCELL);
    int acc = 0;
    for (int c = lo; c < hi; c++) acc += g_ccnt[g][c];
    int v = acc;
    #pragma unroll
    for (int o = 1; o < 32; o <<= 1) { int t = __shfl_up_sync(FULLM, v, o); if (lane >= o) v += t; }
    if (lane == 31) s_warpsum[wid] = v;
    __syncthreads();
    if (wid == 0) {
        int wv = s_warpsum[lane];
        int w2 = wv;
        #pragma unroll
        for (int o = 1; o < 32; o <<= 1) { int t = __shfl_up_sync(FULLM, w2, o); if (lane >= o) w2 += t; }
        s_warpsum[lane] = w2 - wv;
    }
    __syncthreads();
    int run = (v - acc) + s_warpsum[wid];
    for (int c = lo; c < hi; c++) {
        int t = g_ccnt[g][c];
        g_cstart[g][c] = run;
        g_cellfill[g][c] = run;
        g_ccnt[g][c] = 0;            // zero-after-use for next replay
        run += t;
    }
    // Exactly ONE thread (the one covering the last cell) writes the total.
    if (hi == NCELL && lo < NCELL) g_cstart[g][NCELL] = run;
}

// ---------------------------------------------------------------------------
// K3 wide: scatter compacted arrays + cell-sorted SoA
// ---------------------------------------------------------------------------
__global__ void k_scatter(const float* __restrict__ pred,
                          const float* __restrict__ tgt) {
    int g = blockIdx.y, ch = blockIdx.x, tid = threadIdx.x;
    int lane = tid & 31, wid = tid >> 5;
    int b = g >> 1, e = g & 1;
    int CX, CY, CZ; gdims(e, CX, CY, CZ);
    float fx = CX / 25.0f, fy = CY / 25.0f, fz = CZ / 3.0f;
    __shared__ int s_w1[8], s_w2[8];

    int cell = ch * 256 + tid;
    int i = cell >> 8, j = (cell >> 3) & 31, k = cell & 7;
    float4 pv = ((const float4*)pred)[(b * NC + cell) * 2 + e];
    float4 tv = ((const float4*)tgt)[(b * NC + cell) * 2 + e];
    int mp = pv.w > 0.5f;
    int mt = tv.w > 0.5f;

    unsigned bp = __ballot_sync(FULLM, mp);
    unsigned bt = __ballot_sync(FULLM, mt);
    if (lane == 0) { s_w1[wid] = __popc(bp); s_w2[wid] = __popc(bt); }
    __syncthreads();
    int offp = g_chunkBaseP[g][ch], offt = g_chunkBaseT[g][ch];
    for (int x = 0; x < wid; x++) { offp += s_w1[x]; offt += s_w2[x]; }
    offp += __popc(bp & ((1u << lane) - 1u));
    offt += __popc(bt & ((1u << lane) - 1u));

    if (mp) {
        float px = __fmul_rn(__fadd_rn(pv.x, (float)i), LATX);
        float py = __fmul_rn(__fadd_rn(pv.y, (float)j), LATY);
        float pz = __fmul_rn(__fadd_rn(pv.z, (float)k), LATZ);
        float q = sqnorm3(px, py, pz);
        ((float4*)g_praw[g])[offp] = pv;
        g_ppos[g][offp][0] = px; g_ppos[g][offp][1] = py; g_ppos[g][offp][2] = pz;
        g_qp[g][offp] = q;
        int c; cellOf(px, py, pz, fx, fy, fz, CX, CY, CZ, c);
        int p = atomicAdd(&g_cellfill[g][c], 1);
        g_sx[g][p] = px; g_sy[g][p] = py; g_sz[g][p] = pz; g_sq[g][p] = q;
        g_skey[g][p] = ((unsigned long long)__float_as_uint(pv.w) << 32) | (unsigned)offp;
        g_sorig[g][p] = offp;
        g_scell[g][p] = c;
    }
    if (mt) {
        float tx = __fmul_rn(__fadd_rn(tv.x, (float)i), LATX);
        float ty = __fmul_rn(__fadd_rn(tv.y, (float)j), LATY);
        float tz = __fmul_rn(__fadd_rn(tv.z, (float)k), LATZ);
        ((float4*)g_traw[g])[offt] = tv;
        g_tpos[g][offt][0] = tx; g_tpos[g][offt][1] = ty; g_tpos[g][offt][2] = tz;
        g_qt[g][offt] = sqnorm3(tx, ty, tz);
    }
}

// ---------------------------------------------------------------------------
// K4/K5 wide: restrain==0 / sel (+ kept-key collect fused into sel)
// ---------------------------------------------------------------------------
template<int CHECK_R0>
__device__ __forceinline__ int flagScan(int g, int jj, int CX, int CY, int CZ, float S2) {
    float xj = g_sx[g][jj], yj = g_sy[g][jj], zj = g_sz[g][jj], qj = g_sq[g][jj];
    unsigned long long kj = g_skey[g][jj];
    int c = g_scell[g][jj];
    int cz = c % CZ, cy = (c / CZ) % CY, cx = c / (CZ * CY);
    int z0 = max(cz - 1, 0), z1 = min(cz + 1, CZ - 1);
    int ok = 1;
    for (int ax = max(cx - 1, 0); ax <= min(cx + 1, CX - 1) && ok; ax++)
    for (int ay = max(cy - 1, 0); ay <= min(cy + 1, CY - 1) && ok; ay++) {
        int rowc = (ax * CY + ay) * CZ;
        int p1 = g_cstart[g][rowc + z1 + 1];
        for (int p = g_cstart[g][rowc + z0]; p < p1; p++) {
            if (CHECK_R0 && !g_r0s[g][p]) continue;
            if (g_skey[g][p] < kj) {
                float s = dist2(g_sq[g][p], qj, g_sx[g][p], g_sy[g][p], g_sz[g][p],
                                xj, yj, zj);
                if (s < S2) { ok = 0; break; }
            }
        }
    }
    return ok;
}

__global__ void k_res0() {
    int g = blockIdx.y;
    int jj = blockIdx.x * blockDim.x + threadIdx.x;
    if (jj >= g_np[g]) return;
    int e = g & 1;
    int CX, CY, CZ; gdims(e, CX, CY, CZ);
    float S2 = sqr_thresh(e ? DIAM1 : DIAM0);
    g_r0s[g][jj] = (unsigned char)flagScan<0>(g, jj, CX, CY, CZ, S2);
}

__global__ void k_sel() {
    int g = blockIdx.y;
    int jj = blockIdx.x * blockDim.x + threadIdx.x;
    if (jj >= g_np[g]) return;
    int e = g & 1;
    int CX, CY, CZ; gdims(e, CX, CY, CZ);
    float S2 = sqr_thresh(e ? DIAM1 : DIAM0);
    if (flagScan<1>(g, jj, CX, CY, CZ, S2)) {
        int p = atomicAdd(&g_nkc[g], 1);
        g_kkey[g][p] = g_skey[g][jj];
    }
}

// ---------------------------------------------------------------------------
// K6 (16 blocks x 1024): sort kept keys + gather + kept grid
// ---------------------------------------------------------------------------
__global__ void __launch_bounds__(1024, 1) k_sortkept() {
    const int g = blockIdx.x;
    const int e = g & 1;
    const int tid = threadIdx.x, lane = tid & 31, wid = tid >> 5;
    int CX, CY, CZ; gdims(e, CX, CY, CZ);
    const int NCELL = CX * CY * CZ;
    const float fx = CX / 25.0f, fy = CY / 25.0f, fz = CZ / 3.0f;
    const int nk = g_nkc[g];

    __shared__ __align__(8) unsigned char buf[32768];
    unsigned long long* sk = (unsigned long long*)buf;
    int* cnt = (int*)buf;
    __shared__ int s_warpsum[32];

    if (nk <= 4096) {
        int M = 2; while (M < nk) M <<= 1;
        for (int i = tid; i < M; i += 1024) sk[i] = (i < nk) ? g_kkey[g][i] : ~0ull;
        __syncthreads();
        for (int k = 2; k <= M; k <<= 1)
            for (int j = k >> 1; j > 0; j >>= 1) {
                for (int i = tid; i < M; i += 1024) {
                    int l = i ^ j;
                    if (l > i) {
                        unsigned long long a = sk[i], bb = sk[l];
                        bool asc = ((i & k) == 0);
                        if ((a > bb) == asc) { sk[i] = bb; sk[l] = a; }
                    }
                }
                __syncthreads();
            }
        for (int r = tid; r < nk; r += 1024) {
            int src = (int)(sk[r] & 0xffffffffull);
            g_nsrc[g][r] = src;
            g_npos[g][r][0] = g_ppos[g][src][0];
            g_npos[g][r][1] = g_ppos[g][src][1];
            g_npos[g][r][2] = g_ppos[g][src][2];
            g_nq[g][r] = g_qp[g][src];
        }
    } else {
        for (int i = tid; i < nk; i += 1024) {
            unsigned long long ki = g_kkey[g][i];
            int rank = 0;
            for (int j2 = 0; j2 < nk; j2++) rank += (g_kkey[g][j2] < ki);
            int src = (int)(ki & 0xffffffffull);
            g_nsrc[g][rank] = src;
            g_npos[g][rank][0] = g_ppos[g][src][0];
            g_npos[g][rank][1] = g_ppos[g][src][1];
            g_npos[g][rank][2] = g_ppos[g][src][2];
            g_nq[g][rank] = g_qp[g][src];
        }
    }
    __syncthreads();

    // kept grid
    for (int c = tid; c < NCELL; c += 1024) cnt[c] = 0;
    __syncthreads();
    for (int r = tid; r < nk; r += 1024) {
        int c; cellOf(g_npos[g][r][0], g_npos[g][r][1], g_npos[g][r][2],
                      fx, fy, fz, CX, CY, CZ, c);
        atomicAdd(&cnt[c], 1);
    }
    __syncthreads();
    {
        const int CH = 5;
        int lo = tid * CH, hi = min(lo + CH, NCELL);
        int acc = 0;
        for (int c = lo; c < hi; c++) acc += cnt[c];
        int v = acc;
        #pragma unroll
        for (int o = 1; o < 32; o <<= 1) { int t = __shfl_up_sync(FULLM, v, o); if (lane >= o) v += t; }
        if (lane == 31) s_warpsum[wid] = v;
        __syncthreads();
        if (wid == 0) {
            int wv = s_warpsum[lane];
            int w2 = wv;
            #pragma unroll
            for (int o = 1; o < 32; o <<= 1) { int t = __shfl_up_sync(FULLM, w2, o); if (lane >= o) w2 += t; }
            s_warpsum[lane] = w2 - wv;
        }
        __syncthreads();
        int run = (v - acc) + s_warpsum[wid];
        for (int c = lo; c < hi; c++) { int t = cnt[c]; g_kstart[g][c] = run; cnt[c] = run; run += t; }
        if (tid == 0) g_kstart[g][NCELL] = nk;
    }
    __syncthreads();
    for (int r = tid; r < nk; r += 1024) {
        int c; cellOf(g_npos[g][r][0], g_npos[g][r][1], g_npos[g][r][2],
                      fx, fy, fz, CX, CY, CZ, c);
        int p = atomicAdd(&cnt[c], 1);
        g_kxx[g][p] = g_npos[g][r][0];
        g_kyy[g][p] = g_npos[g][r][1];
        g_kzz[g][p] = g_npos[g][r][2];
        g_kqq[g][p] = g_nq[g][r];
        g_klist[g][p] = r;
    }
    if (tid == 0) g_nn[g] = nk;
}

// ---------------------------------------------------------------------------
// K7 wide: match
// ---------------------------------------------------------------------------
__global__ void k_match() {
    int g = blockIdx.y;
    int t = blockIdx.x * blockDim.x + threadIdx.x;
    if (t >= g_nt[g]) return;
    int e = g & 1;
    int CX, CY, CZ; gdims(e, CX, CY, CZ);
    float S2 = sqr_thresh(e ? DIAM1 : DIAM0);
    float fx = CX / 25.0f, fy = CY / 25.0f, fz = CZ / 3.0f;
    float tx = g_tpos[g][t][0], ty = g_tpos[g][t][1], tz = g_tpos[g][t][2];
    float qt = g_qt[g][t];
    int cx = min(max((int)(tx * fx), 0), CX - 1);
    int cy = min(max((int)(ty * fy), 0), CY - 1);
    int cz = min(max((int)(tz * fz), 0), CZ - 1);
    int z0 = max(cz - 1, 0), z1 = min(cz + 1, CZ - 1);
    int x0 = max(cx - 1, 0), x1 = min(cx + 1, CX - 1);
    int y0 = max(cy - 1, 0), y1 = min(cy + 1, CY - 1);

    {
        int any = 0; float bs = __int_as_float(0x7f800000); int bi = 0x7fffffff;
        for (int ax = x0; ax <= x1; ax++)
        for (int ay = y0; ay <= y1; ay++) {
            int rowc = (ax * CY + ay) * CZ;
            int p1 = g_cstart[g][rowc + z1 + 1];
            for (int p = g_cstart[g][rowc + z0]; p < p1; p++) {
                float s = dist2(qt, g_sq[g][p], tx, ty, tz,
                                g_sx[g][p], g_sy[g][p], g_sz[g][p]);
                s = fmaxf(s, 0.0f);
                int jj = g_sorig[g][p];
                any |= (s < S2);
                if (s < bs) {
                    bi = (sqrtf(s) == sqrtf(bs)) ? min(bi, jj) : jj;
                    bs = s;
                } else if (jj < bi && s <= __fmul_rn(bs, 1.000001f)) {
                    if (sqrtf(s) == sqrtf(bs)) bi = jj;
                }
            }
        }
        g_m[g][t] = any; g_piv[g][t] = (bi == 0x7fffffff) ? 0 : bi;
    }
    {
        int any = 0; float bs = __int_as_float(0x7f800000); int bi = 0x7fffffff;
        for (int ax = x0; ax <= x1; ax++)
        for (int ay = y0; ay <= y1; ay++) {
            int rowc = (ax * CY + ay) * CZ;
            int p1 = g_kstart[g][rowc + z1 + 1];
            for (int p = g_kstart[g][rowc + z0]; p < p1; p++) {
                float s = dist2(qt, g_kqq[g][p], tx, ty, tz,
                                g_kxx[g][p], g_kyy[g][p], g_kzz[g][p]);
                s = fmaxf(s, 0.0f);
                int jj = g_klist[g][p];
                any |= (s < S2);
                if (s < bs) {
                    bi = (sqrtf(s) == sqrtf(bs)) ? min(bi, jj) : jj;
                    bs = s;
                } else if (jj < bi && s <= __fmul_rn(bs, 1.000001f)) {
                    if (sqrtf(s) == sqrtf(bs)) bi = jj;
                }
            }
        }
        g_mn[g][t] = any; g_pinv[g][t] = (bi == 0x7fffffff) ? 0 : bi;
    }
}

// ---------------------------------------------------------------------------
// K8 (16 blocks x 256): compact matches
// ---------------------------------------------------------------------------
__global__ void k_post() {
    int g = blockIdx.x;
    int tid = threadIdx.x;
    int lane = tid & 31, w = tid >> 5;
    int Nt = g_nt[g];
    __shared__ int wt[8];
    __shared__ int base;

    for (int pass = 0; pass < 2; pass++) {
        if (tid == 0) base = 0;
        __syncthreads();
        for (int cb = 0; cb < Nt; cb += 256) {
            int t = cb + tid;
            int f = 0;
            if (t < Nt) f = pass ? g_mn[g][t] : g_m[g][t];
            unsigned bl = __ballot_sync(FULLM, f != 0);
            if (lane == 0) wt[w] = __popc(bl);
            __syncthreads();
            int off = base;
            for (int x = 0; x < w; x++) off += wt[x];
            off += __popc(bl & ((1u << lane) - 1u));
            if (f) {
                if (pass) { g_tin[g][off] = t; g_pin[g][off] = g_pinv[g][t]; }
                else      { g_ti[g][off]  = t; g_pi[g][off]  = g_piv[g][t]; }
            }
            __syncthreads();
            if (tid == 0) { int s = 0; for (int x = 0; x < 8; x++) s += wt[x]; base += s; }
            __syncthreads();
        }
        if (tid == 0) { if (pass) g_kn[g] = base; else g_k[g] = base; }
        __syncthreads();
    }
}

// ---------------------------------------------------------------------------
// K9 wide: write output (base computed locally per block)
// ---------------------------------------------------------------------------
__global__ void k_write(float* __restrict__ out) {
    int g = blockIdx.y;
    __shared__ long long s_base;
    __shared__ int s_sz[5];
    if (threadIdx.x == 0) {
        long long base = 0;
        for (int g2 = 0; g2 < g; g2++) {
            long long Np = g_np[g2], Nn = g_nn[g2], Nt = g_nt[g2];
            long long K = g_k[g2], Kn = g_kn[g2];
            base += Np * 7 + Nn * 7 + Nt * 7 + 2 * K + 2 * Kn;
        }
        s_base = base;
        s_sz[0] = g_np[g]; s_sz[1] = g_nn[g]; s_sz[2] = g_nt[g];
        s_sz[3] = g_k[g];  s_sz[4] = g_kn[g];
    }
    __syncthreads();
    long long base = s_base;
    int Np = s_sz[0], Nn = s_sz[1], Nt = s_sz[2], K = s_sz[3], Kn = s_sz[4];
    int T = Np * 7 + Nn * 7 + Nt * 7 + 2 * K + 2 * Kn;
    int stride = gridDim.x * blockDim.x;
    for (int idx = blockIdx.x * blockDim.x + threadIdx.x; idx < T; idx += stride) {
        int o = idx;
        float v;
        if (o < Np * 4) { v = g_praw[g][o >> 2][o & 3]; }
        else {
            o -= Np * 4;
            if (o < Nn * 4) { v = g_praw[g][g_nsrc[g][o >> 2]][o & 3]; }
            else {
                o -= Nn * 4;
                if (o < Nt * 4) { v = g_traw[g][o >> 2][o & 3]; }
                else {
                    o -= Nt * 4;
                    if (o < K) { v = (float)g_ti[g][o]; }
                    else {
                        o -= K;
                        if (o < K) { v = (float)g_pi[g][o]; }
                        else {
                            o -= K;
                            if (o < Kn) { v = (float)g_tin[g][o]; }
                            else {
                                o -= Kn;
                                if (o < Kn) { v = (float)g_pin[g][o]; }
                                else {
                                    o -= Kn;
                                    if (o < Np * 3) { v = g_ppos[g][o / 3][o % 3]; }
                                    else {
                                        o -= Np * 3;
                                        if (o < Nn * 3) { v = g_npos[g][o / 3][o % 3]; }
                                        else { o -= Nn * 3; v = g_tpos[g][o / 3][o % 3]; }
                                    }
                                }
                            }
                        }
                    }
                }
            }
        }
        out[base + idx] = v;
    }
}

// ---------------------------------------------------------------------------
// launch: 9 graph nodes
// ---------------------------------------------------------------------------
extern "C" void kernel_launch(void* const* d_in, const int* in_sizes, int n_in,
                              void* d_out, int out_size) {
    const float* pred = (const float*)d_in[0];
    const float* tgt  = (const float*)d_in[1];
    float* out = (float*)d_out;
    (void)in_sizes; (void)n_in; (void)out_size;

    dim3 wide(NCHUNK, NG);
    k_count<<<wide, 256>>>(pred, tgt);
    k_scan<<<NG, 1024>>>();
    k_scatter<<<wide, 256>>>(pred, tgt);
    k_res0<<<wide, 256>>>();
    k_sel<<<wide, 256>>>();
    k_sortkept<<<NG, 1024>>>();
    k_match<<<wide, 256>>>();
    k_post<<<NG, 256>>>();
    k_write<<<wide, 256>>>(out);
}